// round 2
// baseline (speedup 1.0000x reference)
#include <cuda_runtime.h>
#include <cuda_bf16.h>
#include <float.h>

#define NEXP 64
#define TPB  256

__global__ void __launch_bounds__(TPB)
optix_route_kernel(const float* __restrict__ pos,
                   const float* __restrict__ centers,
                   const float* __restrict__ radii,
                   float* __restrict__ out_probs,
                   float* __restrict__ out_ids,
                   int B, int write_ids)
{
    __shared__ float4 sc[NEXP];      // (cx, cy, cz, safe_r)
    __shared__ int    sids[TPB];

    const int tid = threadIdx.x;

    // ---- preload centers + safe radii into shared ----
    if (tid < NEXP) {
        float cx = centers[3 * tid + 0];
        float cy = centers[3 * tid + 1];
        float cz = centers[3 * tid + 2];
        float r  = fmaxf(fabsf(radii[tid]), 0.01f);
        sc[tid] = make_float4(cx, cy, cz, r);
    }
    __syncthreads();

    // ---- phase 1: per-thread argmax over 64 experts, faithful fp32 sequence ----
    const long long gpos = (long long)blockIdx.x * TPB + tid;
    int id = 0;
    if (gpos < B) {
        const float px = pos[3 * gpos + 0];
        const float py = pos[3 * gpos + 1];
        const float pz = pos[3 * gpos + 2];

        float l[NEXP];
        float m  = -FLT_MAX;
        #pragma unroll
        for (int e = 0; e < NEXP; e++) {
            float4 c = sc[e];
            // exact replication of: diff = p - c; d2 = sum(diff*diff); dist = sqrt(d2+1e-12)
            // logits = 10 * (r - dist).  No FMA contraction (XLA mul + sequential reduce).
            float dx = __fsub_rn(px, c.x);
            float dy = __fsub_rn(py, c.y);
            float dz = __fsub_rn(pz, c.z);
            float d2 = __fadd_rn(__fadd_rn(__fmul_rn(dx, dx), __fmul_rn(dy, dy)),
                                 __fmul_rn(dz, dz));
            float dist = __fsqrt_rn(__fadd_rn(d2, 1e-12f));
            float li   = __fmul_rn(10.0f, __fsub_rn(c.w, dist));
            l[e] = li;
            if (li > m) { m = li; }   // track max value only
        }
        // softmax tie band: exp(l - m) rounds to 1.0f when (m - l) <= ~2^-25,
        // so argmax(softmax(l)) returns the FIRST index inside that band.
        const float band = 2.9802322e-8f;  // 2^-25
        #pragma unroll
        for (int e = 0; e < NEXP; e++) {
            if (__fsub_rn(m, l[e]) <= band) { id = e; break; }
        }
    }
    sids[tid] = id;
    __syncthreads();

    // ---- phase 2: coalesced one-hot tile write (256 rows x 64 cols as float4) ----
    const long long rowbase = (long long)blockIdx.x * TPB;
    float4* __restrict__ outv = (float4*)out_probs;   // 16 float4 per row
    #pragma unroll
    for (int k = 0; k < 16; k++) {
        int idx = k * TPB + tid;          // 0 .. 4095
        int row = idx >> 4;               // local row 0..255
        int c4  = idx & 15;               // float4 column 0..15
        long long grow = rowbase + row;
        if (grow < B) {
            int eid  = sids[row];
            int base = c4 << 2;
            float4 v;
            v.x = (eid == base + 0) ? 1.0f : 0.0f;
            v.y = (eid == base + 1) ? 1.0f : 0.0f;
            v.z = (eid == base + 2) ? 1.0f : 0.0f;
            v.w = (eid == base + 3) ? 1.0f : 0.0f;
            outv[grow * 16 + c4] = v;
        }
    }

    if (write_ids && gpos < B) {
        out_ids[gpos] = (float)id;
    }
}

extern "C" void kernel_launch(void* const* d_in, const int* in_sizes, int n_in,
                              void* d_out, int out_size)
{
    const float* pos     = (const float*)d_in[0];   // positions_3d (B,3)
    const float* centers = (const float*)d_in[1];   // centers (64,3)
    const float* radii   = (const float*)d_in[2];   // radii (64,)

    int B = in_sizes[0] / 3;
    float* out_probs = (float*)d_out;
    // adaptive output layout: probs only (B*64) vs probs + ids (B*65)
    long long need_ids = (long long)B * (NEXP + 1);
    int write_ids = ((long long)out_size >= need_ids) ? 1 : 0;
    float* out_ids = out_probs + (long long)B * NEXP;

    int grid = (B + TPB - 1) / TPB;
    optix_route_kernel<<<grid, TPB>>>(pos, centers, radii, out_probs, out_ids, B, write_ids);
}